// round 7
// baseline (speedup 1.0000x reference)
#include <cuda_runtime.h>
#include <cstdint>
#include <cstddef>

// ---------------------------------------------------------------------------
// Problem constants (hardcoded from reference)
// ---------------------------------------------------------------------------
#define NB   4          // batch
#define LQ   8192       // queries
#define DM   256        // model dim
#define LIN  21760      // sum of level sizes
#define NHD  8          // heads
#define HD   32         // head dim
#define DFF  1024       // ffn dim
#define NROW (NB*LQ)    // 32768 query rows
#define VROW (NB*LIN)   // 87040 value rows

__constant__ int   c_lvl_start[4] = {0, 16384, 20480, 21504};
__constant__ float c_lvl_wh[4]    = {128.f, 64.f, 32.f, 16.f}; // square levels

// ---------------------------------------------------------------------------
// Scratch (static device memory; liveness-based reuse, 240 MB)
//   region A (8,388,608 floats) : sampled
//   region B (34,865,152 floats): value|off|aw -> ffn hidden h (33,554,432)
//   region C (8,388,608 floats) : x1
//   region D (8,388,608 floats) : h2 / attn_out
// ---------------------------------------------------------------------------
#define OFF_A    ((size_t)0)
#define OFF_B    ((size_t)8388608)
#define OFF_VAL  (OFF_B)
#define OFF_OFF  (OFF_B + (size_t)22282240)
#define OFF_AW   (OFF_B + (size_t)30670848)
#define OFF_C    ((size_t)43253760)
#define OFF_D    ((size_t)51642368)
#define SCRATCH_FLOATS ((size_t)60030976)

__device__ float g_scratch[SCRATCH_FLOATS];

// ---------------------------------------------------------------------------
// TF32 tensor-core GEMM: C[M,N] = A[M,K] @ B[K,N] + bias[N]
//  EPI = 0 : bias only
//  EPI = 1 : bias + relu
//  EPI = 2 : bias, then zero row if mask[m] != 0
//  FUSE_ADD: A is read as A[i] + A2[i] (fused residual/pos add on the fly)
// 128x128 block tile, BK=16, 256 threads (8 warps), warp tile 64x32 built
// from mma.sync.m16n8k8.tf32. Double-buffered smem (2-stage): smem fill of
// tile k+1 overlaps MMA of tile k; one __syncthreads per K-tile.
// A stored k-major As[k][m], B as Bs[k][n], stride 136 (conflict-free).
// fp32->tf32 conversion at the global->shared store.
// Requires M%128==0, N%128==0, K%16==0.
// ---------------------------------------------------------------------------
#define TG_STRIDE 136
#define TG_BUF    (16 * TG_STRIDE)

__device__ __forceinline__ uint32_t f2tf32(float f) {
    uint32_t u;
    asm("cvt.rna.tf32.f32 %0, %1;" : "=r"(u) : "f"(f));
    return u;
}

__device__ __forceinline__ void mma_tf32(float d[4], const uint32_t a[4],
                                         const uint32_t b[2]) {
    asm volatile(
        "mma.sync.aligned.m16n8k8.row.col.f32.tf32.tf32.f32 "
        "{%0,%1,%2,%3}, {%4,%5,%6,%7}, {%8,%9}, {%0,%1,%2,%3};"
        : "+f"(d[0]), "+f"(d[1]), "+f"(d[2]), "+f"(d[3])
        : "r"(a[0]), "r"(a[1]), "r"(a[2]), "r"(a[3]), "r"(b[0]), "r"(b[1]));
}

template<int EPI, bool FUSE_ADD>
__global__ __launch_bounds__(256, 2)
void tgemm_kernel(int M, int Nn, int K,
                  const float* __restrict__ A, const float* __restrict__ A2,
                  const float* __restrict__ B,
                  const float* __restrict__ bias, float* __restrict__ C,
                  const unsigned char* __restrict__ mask)
{
    const int BK = 16;
    __shared__ uint32_t As[2 * TG_BUF];   // [stage][k][m]
    __shared__ uint32_t Bs[2 * TG_BUF];   // [stage][k][n]

    const int t    = threadIdx.x;
    const int m0   = blockIdx.y * 128;
    const int n0   = blockIdx.x * 128;
    const int w    = t >> 5;
    const int lane = t & 31;
    const int g    = lane >> 2;      // groupID 0..7
    const int c    = lane & 3;       // threadID_in_group 0..3
    const int warp_m = (w & 1) * 64;
    const int warp_n = (w >> 1) * 32;

    // global->shared loader mapping
    const int aRow = t & 127;        // A row within tile
    const int ks   = (t >> 7) * 8;   // k offset 0 or 8
    const int bRow = t >> 4;         // B k-row 0..15
    const int bCol = (t & 15) * 8;   // B col 0..120

    const float* aPtr  = &A[(size_t)(m0 + aRow) * K + ks];
    const float* a2Ptr = FUSE_ADD ? &A2[(size_t)(m0 + aRow) * K + ks] : nullptr;
    const float* bPtr  = &B[(size_t)bRow * Nn + n0 + bCol];
    const size_t bStep = (size_t)Nn;

    float acc[4][4][4];
    #pragma unroll
    for (int mt = 0; mt < 4; mt++)
        #pragma unroll
        for (int nt = 0; nt < 4; nt++)
            #pragma unroll
            for (int r = 0; r < 4; r++) acc[mt][nt][r] = 0.f;

    // ---- fetch tile 0 into registers ----
    float4 ra0 = *(const float4*)(aPtr);
    float4 ra1 = *(const float4*)(aPtr + 4);
    if (FUSE_ADD) {
        float4 s0 = *(const float4*)(a2Ptr);
        float4 s1 = *(const float4*)(a2Ptr + 4);
        ra0.x += s0.x; ra0.y += s0.y; ra0.z += s0.z; ra0.w += s0.w;
        ra1.x += s1.x; ra1.y += s1.y; ra1.z += s1.z; ra1.w += s1.w;
    }
    float4 rb0 = *(const float4*)(bPtr);
    float4 rb1 = *(const float4*)(bPtr + 4);

    // ---- store tile 0 to stage 0 ----
    {
        uint32_t* as0 = As;
        uint32_t* bs0 = Bs;
        as0[(ks + 0) * TG_STRIDE + aRow] = f2tf32(ra0.x);
        as0[(ks + 1) * TG_STRIDE + aRow] = f2tf32(ra0.y);
        as0[(ks + 2) * TG_STRIDE + aRow] = f2tf32(ra0.z);
        as0[(ks + 3) * TG_STRIDE + aRow] = f2tf32(ra0.w);
        as0[(ks + 4) * TG_STRIDE + aRow] = f2tf32(ra1.x);
        as0[(ks + 5) * TG_STRIDE + aRow] = f2tf32(ra1.y);
        as0[(ks + 6) * TG_STRIDE + aRow] = f2tf32(ra1.z);
        as0[(ks + 7) * TG_STRIDE + aRow] = f2tf32(ra1.w);
        bs0[bRow * TG_STRIDE + bCol + 0] = f2tf32(rb0.x);
        bs0[bRow * TG_STRIDE + bCol + 1] = f2tf32(rb0.y);
        bs0[bRow * TG_STRIDE + bCol + 2] = f2tf32(rb0.z);
        bs0[bRow * TG_STRIDE + bCol + 3] = f2tf32(rb0.w);
        bs0[bRow * TG_STRIDE + bCol + 4] = f2tf32(rb1.x);
        bs0[bRow * TG_STRIDE + bCol + 5] = f2tf32(rb1.y);
        bs0[bRow * TG_STRIDE + bCol + 6] = f2tf32(rb1.z);
        bs0[bRow * TG_STRIDE + bCol + 7] = f2tf32(rb1.w);
    }
    __syncthreads();

    const int nTiles = K / BK;
    for (int kt = 0; kt < nTiles; kt++) {
        const uint32_t* asr = As + (kt & 1) * TG_BUF;
        const uint32_t* bsr = Bs + (kt & 1) * TG_BUF;

        // prefetch next tile into registers (latency hidden by MMA below)
        const bool more = (kt + 1 < nTiles);
        if (more) {
            const float* ap = aPtr + (kt + 1) * BK;
            const float* bp = bPtr + (size_t)(kt + 1) * BK * bStep;
            ra0 = *(const float4*)(ap);
            ra1 = *(const float4*)(ap + 4);
            if (FUSE_ADD) {
                const float* ap2 = a2Ptr + (kt + 1) * BK;
                float4 s0 = *(const float4*)(ap2);
                float4 s1 = *(const float4*)(ap2 + 4);
                ra0.x += s0.x; ra0.y += s0.y; ra0.z += s0.z; ra0.w += s0.w;
                ra1.x += s1.x; ra1.y += s1.y; ra1.z += s1.z; ra1.w += s1.w;
            }
            rb0 = *(const float4*)(bp);
            rb1 = *(const float4*)(bp + 4);
        }

        // compute current tile
        #pragma unroll
        for (int kk = 0; kk < BK; kk += 8) {
            uint32_t afr[4][4];
            #pragma unroll
            for (int mt = 0; mt < 4; mt++) {
                const int m = warp_m + mt * 16 + g;
                afr[mt][0] = asr[(kk + c) * TG_STRIDE + m];
                afr[mt][1] = asr[(kk + c) * TG_STRIDE + m + 8];
                afr[mt][2] = asr[(kk + c + 4) * TG_STRIDE + m];
                afr[mt][3] = asr[(kk + c + 4) * TG_STRIDE + m + 8];
            }
            uint32_t bfr[4][2];
            #pragma unroll
            for (int nt = 0; nt < 4; nt++) {
                const int n = warp_n + nt * 8 + g;
                bfr[nt][0] = bsr[(kk + c) * TG_STRIDE + n];
                bfr[nt][1] = bsr[(kk + c + 4) * TG_STRIDE + n];
            }
            #pragma unroll
            for (int mt = 0; mt < 4; mt++)
                #pragma unroll
                for (int nt = 0; nt < 4; nt++)
                    mma_tf32(acc[mt][nt], afr[mt], bfr[nt]);
        }

        // store next tile into the other stage, single sync
        if (more) {
            uint32_t* asw = As + ((kt + 1) & 1) * TG_BUF;
            uint32_t* bsw = Bs + ((kt + 1) & 1) * TG_BUF;
            asw[(ks + 0) * TG_STRIDE + aRow] = f2tf32(ra0.x);
            asw[(ks + 1) * TG_STRIDE + aRow] = f2tf32(ra0.y);
            asw[(ks + 2) * TG_STRIDE + aRow] = f2tf32(ra0.z);
            asw[(ks + 3) * TG_STRIDE + aRow] = f2tf32(ra0.w);
            asw[(ks + 4) * TG_STRIDE + aRow] = f2tf32(ra1.x);
            asw[(ks + 5) * TG_STRIDE + aRow] = f2tf32(ra1.y);
            asw[(ks + 6) * TG_STRIDE + aRow] = f2tf32(ra1.z);
            asw[(ks + 7) * TG_STRIDE + aRow] = f2tf32(ra1.w);
            bsw[bRow * TG_STRIDE + bCol + 0] = f2tf32(rb0.x);
            bsw[bRow * TG_STRIDE + bCol + 1] = f2tf32(rb0.y);
            bsw[bRow * TG_STRIDE + bCol + 2] = f2tf32(rb0.z);
            bsw[bRow * TG_STRIDE + bCol + 3] = f2tf32(rb0.w);
            bsw[bRow * TG_STRIDE + bCol + 4] = f2tf32(rb1.x);
            bsw[bRow * TG_STRIDE + bCol + 5] = f2tf32(rb1.y);
            bsw[bRow * TG_STRIDE + bCol + 6] = f2tf32(rb1.z);
            bsw[bRow * TG_STRIDE + bCol + 7] = f2tf32(rb1.w);
            __syncthreads();
        }
    }

    // epilogue: bias (+relu / +mask) and store
    #pragma unroll
    for (int mt = 0; mt < 4; mt++) {
        const int r0 = m0 + warp_m + mt * 16 + g;
        const int r1 = r0 + 8;
        float mf0 = 1.f, mf1 = 1.f;
        if (EPI == 2) {
            mf0 = mask[r0] ? 0.f : 1.f;
            mf1 = mask[r1] ? 0.f : 1.f;
        }
        #pragma unroll
        for (int nt = 0; nt < 4; nt++) {
            const int col = n0 + warp_n + nt * 8 + c * 2;
            const float2 bv = *(const float2*)&bias[col];
            float2 v0, v1;
            v0.x = acc[mt][nt][0] + bv.x;
            v0.y = acc[mt][nt][1] + bv.y;
            v1.x = acc[mt][nt][2] + bv.x;
            v1.y = acc[mt][nt][3] + bv.y;
            if (EPI == 1) {
                v0.x = fmaxf(v0.x, 0.f); v0.y = fmaxf(v0.y, 0.f);
                v1.x = fmaxf(v1.x, 0.f); v1.y = fmaxf(v1.y, 0.f);
            }
            if (EPI == 2) {
                v0.x *= mf0; v0.y *= mf0;
                v1.x *= mf1; v1.y *= mf1;
            }
            *(float2*)&C[(size_t)r0 * Nn + col] = v0;
            *(float2*)&C[(size_t)r1 * Nn + col] = v1;
        }
    }
}

// ---------------------------------------------------------------------------
// Deformable sampling. One warp per (n, lq, head). Lane = head channel (0..31).
// Includes warp softmax over the 16 attention logits.
// ---------------------------------------------------------------------------
__global__ __launch_bounds__(256)
void sample_kernel(const float* __restrict__ value,
                   const float* __restrict__ off,
                   const float* __restrict__ aw,
                   const float* __restrict__ refp,
                   float* __restrict__ outp)
{
    const int gwarp = (blockIdx.x * blockDim.x + threadIdx.x) >> 5;
    const int lane  = threadIdx.x & 31;
    const int h     = gwarp & 7;
    const int row   = gwarp >> 3;          // n*LQ + lq
    const int n     = row >> 13;           // LQ = 8192

    // ---- warp softmax over 16 attention logits (lanes 0..15 hold data) ----
    float av = -1e30f;
    if (lane < 16) av = aw[(size_t)row * 128 + h * 16 + lane];
    float mx = av;
    #pragma unroll
    for (int o = 16; o > 0; o >>= 1) mx = fmaxf(mx, __shfl_xor_sync(0xffffffffu, mx, o));
    float e = (lane < 16) ? __expf(av - mx) : 0.f;
    float sm = e;
    #pragma unroll
    for (int o = 16; o > 0; o >>= 1) sm += __shfl_xor_sync(0xffffffffu, sm, o);
    const float w_aw = e / sm;

    // ---- per-sample corner indices / weights (lanes 0..15, sample = lane) --
    int   cidx[4] = {0, 0, 0, 0};
    float cw[4]   = {0.f, 0.f, 0.f, 0.f};
    if (lane < 16) {
        const int l = lane >> 2;
        const float2 of = *(const float2*)&off[(size_t)row * 256 + (h * 16 + lane) * 2];
        const float2 rp = *(const float2*)&refp[((size_t)row * 4 + l) * 2];
        const float Wl = c_lvl_wh[l];
        const float Hl = Wl;               // square levels
        const int   Wi = (int)Wl;
        const int   start = c_lvl_start[l];

        const float x  = (rp.x + of.x / Wl) * Wl - 0.5f;
        const float y  = (rp.y + of.y / Hl) * Hl - 0.5f;
        const float x0 = floorf(x), y0 = floorf(y);
        const float dx = x - x0,   dy = y - y0;

        #pragma unroll
        for (int cc = 0; cc < 4; cc++) {
            const float cx = x0 + (float)(cc & 1);
            const float cy = y0 + (float)(cc >> 1);
            const float wgt = ((cc & 1) ? dx : 1.f - dx) * ((cc >> 1) ? dy : 1.f - dy);
            const bool valid = (cx >= 0.f) && (cx <= Wl - 1.f) &&
                               (cy >= 0.f) && (cy <= Hl - 1.f);
            const int ix = (int)fminf(fmaxf(cx, 0.f), Wl - 1.f);
            const int iy = (int)fminf(fmaxf(cy, 0.f), Hl - 1.f);
            cidx[cc] = start + iy * Wi + ix;
            cw[cc]   = valid ? wgt * w_aw : 0.f;
        }
    }

    // ---- gather + accumulate: 16 samples x 4 corners, lane = channel ------
    const float* vbase = value + (size_t)n * (LIN * 256) + h * 32 + lane;
    float acc = 0.f;
    #pragma unroll
    for (int s = 0; s < 16; s++) {
        #pragma unroll
        for (int cc = 0; cc < 4; cc++) {
            const int   idx = __shfl_sync(0xffffffffu, cidx[cc], s);
            const float wc  = __shfl_sync(0xffffffffu, cw[cc],  s);
            acc += wc * vbase[idx * 256];
        }
    }
    outp[(size_t)row * 256 + h * 32 + lane] = acc;
}

// ---------------------------------------------------------------------------
// Fused residual add + LayerNorm: out = LN(a + b). One warp per row (D=256).
// ---------------------------------------------------------------------------
__global__ __launch_bounds__(256)
void add_ln_kernel(const float* __restrict__ a, const float* __restrict__ b,
                   const float* __restrict__ g, const float* __restrict__ bet,
                   float* __restrict__ outp)
{
    const int row  = (blockIdx.x * blockDim.x + threadIdx.x) >> 5;
    const int lane = threadIdx.x & 31;
    const size_t base = (size_t)row * 256 + lane * 8;

    float v[8];
    float4 a0 = *(const float4*)&a[base];
    float4 a1 = *(const float4*)&a[base + 4];
    float4 b0 = *(const float4*)&b[base];
    float4 b1 = *(const float4*)&b[base + 4];
    v[0] = a0.x + b0.x; v[1] = a0.y + b0.y; v[2] = a0.z + b0.z; v[3] = a0.w + b0.w;
    v[4] = a1.x + b1.x; v[5] = a1.y + b1.y; v[6] = a1.z + b1.z; v[7] = a1.w + b1.w;

    float sum = 0.f, sq = 0.f;
    #pragma unroll
    for (int i = 0; i < 8; i++) { sum += v[i]; sq += v[i] * v[i]; }
    #pragma unroll
    for (int o = 16; o > 0; o >>= 1) {
        sum += __shfl_xor_sync(0xffffffffu, sum, o);
        sq  += __shfl_xor_sync(0xffffffffu, sq,  o);
    }
    const float mean = sum * (1.f / 256.f);
    const float var  = sq * (1.f / 256.f) - mean * mean;
    const float inv  = rsqrtf(var + 1e-5f);

    float4 g0 = *(const float4*)&g[lane * 8];
    float4 g1 = *(const float4*)&g[lane * 8 + 4];
    float4 e0 = *(const float4*)&bet[lane * 8];
    float4 e1 = *(const float4*)&bet[lane * 8 + 4];
    float gv[8] = {g0.x,g0.y,g0.z,g0.w,g1.x,g1.y,g1.z,g1.w};
    float ev[8] = {e0.x,e0.y,e0.z,e0.w,e1.x,e1.y,e1.z,e1.w};

    float o8[8];
    #pragma unroll
    for (int i = 0; i < 8; i++) o8[i] = (v[i] - mean) * inv * gv[i] + ev[i];
    float4 r0 = {o8[0], o8[1], o8[2], o8[3]};
    float4 r1 = {o8[4], o8[5], o8[6], o8[7]};
    *(float4*)&outp[base]     = r0;
    *(float4*)&outp[base + 4] = r1;
}

// ---------------------------------------------------------------------------
// Launch
// ---------------------------------------------------------------------------
extern "C" void kernel_launch(void* const* d_in, const int* in_sizes, int n_in,
                              void* d_out, int out_size)
{
    const float* tgt   = (const float*)d_in[0];
    const float* qpos  = (const float*)d_in[1];
    const float* refp  = (const float*)d_in[2];
    const float* src   = (const float*)d_in[3];
    // d_in[4] src_spatial_shapes (int64), d_in[5] level_start_index (int64): hardcoded
    const unsigned char* pmask = (const unsigned char*)d_in[6];
    const float* W_off = (const float*)d_in[7];
    const float* b_off = (const float*)d_in[8];
    const float* W_att = (const float*)d_in[9];
    const float* b_att = (const float*)d_in[10];
    const float* W_val = (const float*)d_in[11];
    const float* b_val = (const float*)d_in[12];
    const float* W_out = (const float*)d_in[13];
    const float* b_out = (const float*)d_in[14];
    const float* ln1_g = (const float*)d_in[15];
    const float* ln1_b = (const float*)d_in[16];
    const float* W_fc1 = (const float*)d_in[17];
    const float* b_fc1 = (const float*)d_in[18];
    const float* W_fc2 = (const float*)d_in[19];
    const float* b_fc2 = (const float*)d_in[20];
    const float* ln2_g = (const float*)d_in[21];
    const float* ln2_b = (const float*)d_in[22];
    float* out = (float*)d_out;

    float* base = nullptr;
    cudaGetSymbolAddress((void**)&base, g_scratch);
    float* smp = base + OFF_A;     // region A: sampled
    float* val = base + OFF_VAL;   // region B: value|off|aw, later ffn hidden
    float* ofb = base + OFF_OFF;
    float* awb = base + OFF_AW;
    float* hb  = base + OFF_B;
    float* x1  = base + OFF_C;     // region C
    float* h2  = base + OFF_D;     // region D

    // 1. value = mask(src @ W_val + b_val)   M=87040, N=256, K=256
    tgemm_kernel<2, false><<<dim3(2, 680), 256>>>(VROW, DM, DM, src, nullptr, W_val, b_val, val, pmask);
    // 2. off = (tgt+qpos) @ W_off + b_off    M=32768, N=256, K=256 (fused add)
    tgemm_kernel<0, true><<<dim3(2, 256), 256>>>(NROW, DM, DM, tgt, qpos, W_off, b_off, ofb, nullptr);
    // 3. aw  = (tgt+qpos) @ W_attn + b_attn  M=32768, N=128, K=256 (fused add)
    tgemm_kernel<0, true><<<dim3(1, 256), 256>>>(NROW, 128, DM, tgt, qpos, W_att, b_att, awb, nullptr);
    // 4. deformable sampling + softmax
    sample_kernel<<<(NROW * NHD) / 8, 256>>>(val, ofb, awb, refp, smp);
    // 5. attn_out = sampled @ W_out + b_out  -> h2 (region D)
    tgemm_kernel<0, false><<<dim3(2, 256), 256>>>(NROW, DM, DM, smp, nullptr, W_out, b_out, h2, nullptr);
    // 6. x1 = LN1(tgt + attn_out)
    add_ln_kernel<<<NROW / 8, 256>>>(tgt, h2, ln1_g, ln1_b, x1);
    // 7. h = relu(x1 @ W_fc1 + b_fc1)        M=32768, N=1024, K=256 (B region dead -> h)
    tgemm_kernel<1, false><<<dim3(8, 256), 256>>>(NROW, DFF, DM, x1, nullptr, W_fc1, b_fc1, hb, nullptr);
    // 8. h2 = h @ W_fc2 + b_fc2              M=32768, N=256, K=1024
    tgemm_kernel<0, false><<<dim3(2, 256), 256>>>(NROW, DM, DFF, hb, nullptr, W_fc2, b_fc2, h2, nullptr);
    // 9. out = LN2(x1 + h2)
    add_ln_kernel<<<NROW / 8, 256>>>(x1, h2, ln2_g, ln2_b, out);
}

// round 8
// speedup vs baseline: 1.0969x; 1.0969x over previous
#include <cuda_runtime.h>
#include <cstdint>
#include <cstddef>

// ---------------------------------------------------------------------------
// Problem constants (hardcoded from reference)
// ---------------------------------------------------------------------------
#define NB   4          // batch
#define LQ   8192       // queries
#define DM   256        // model dim
#define LIN  21760      // sum of level sizes
#define NHD  8          // heads
#define HD   32         // head dim
#define DFF  1024       // ffn dim
#define NROW (NB*LQ)    // 32768 query rows
#define VROW (NB*LIN)   // 87040 value rows

__constant__ int   c_lvl_start[4] = {0, 16384, 20480, 21504};
__constant__ float c_lvl_wh[4]    = {128.f, 64.f, 32.f, 16.f}; // square levels

// ---------------------------------------------------------------------------
// Scratch (static device memory; liveness-based reuse, 240 MB)
// ---------------------------------------------------------------------------
#define OFF_A    ((size_t)0)
#define OFF_B    ((size_t)8388608)
#define OFF_VAL  (OFF_B)
#define OFF_OFF  (OFF_B + (size_t)22282240)
#define OFF_AW   (OFF_B + (size_t)30670848)
#define OFF_C    ((size_t)43253760)
#define OFF_D    ((size_t)51642368)
#define SCRATCH_FLOATS ((size_t)60030976)

__device__ float g_scratch[SCRATCH_FLOATS];

// ---------------------------------------------------------------------------
// TF32 tensor-core GEMM (unchanged from R7): C = A@B + bias, optional
// relu/mask epilogues and fused A+A2 load. Double-buffered smem, warp tile
// 64x32 of m16n8k8.tf32 MMAs.
// ---------------------------------------------------------------------------
#define TG_STRIDE 136
#define TG_BUF    (16 * TG_STRIDE)

__device__ __forceinline__ uint32_t f2tf32(float f) {
    uint32_t u;
    asm("cvt.rna.tf32.f32 %0, %1;" : "=r"(u) : "f"(f));
    return u;
}

__device__ __forceinline__ void mma_tf32(float d[4], const uint32_t a[4],
                                         const uint32_t b[2]) {
    asm volatile(
        "mma.sync.aligned.m16n8k8.row.col.f32.tf32.tf32.f32 "
        "{%0,%1,%2,%3}, {%4,%5,%6,%7}, {%8,%9}, {%0,%1,%2,%3};"
        : "+f"(d[0]), "+f"(d[1]), "+f"(d[2]), "+f"(d[3])
        : "r"(a[0]), "r"(a[1]), "r"(a[2]), "r"(a[3]), "r"(b[0]), "r"(b[1]));
}

template<int EPI, bool FUSE_ADD>
__global__ __launch_bounds__(256, 2)
void tgemm_kernel(int M, int Nn, int K,
                  const float* __restrict__ A, const float* __restrict__ A2,
                  const float* __restrict__ B,
                  const float* __restrict__ bias, float* __restrict__ C,
                  const unsigned char* __restrict__ mask)
{
    const int BK = 16;
    __shared__ uint32_t As[2 * TG_BUF];   // [stage][k][m]
    __shared__ uint32_t Bs[2 * TG_BUF];   // [stage][k][n]

    const int t    = threadIdx.x;
    const int m0   = blockIdx.y * 128;
    const int n0   = blockIdx.x * 128;
    const int w    = t >> 5;
    const int lane = t & 31;
    const int g    = lane >> 2;
    const int c    = lane & 3;
    const int warp_m = (w & 1) * 64;
    const int warp_n = (w >> 1) * 32;

    const int aRow = t & 127;
    const int ks   = (t >> 7) * 8;
    const int bRow = t >> 4;
    const int bCol = (t & 15) * 8;

    const float* aPtr  = &A[(size_t)(m0 + aRow) * K + ks];
    const float* a2Ptr = FUSE_ADD ? &A2[(size_t)(m0 + aRow) * K + ks] : nullptr;
    const float* bPtr  = &B[(size_t)bRow * Nn + n0 + bCol];
    const size_t bStep = (size_t)Nn;

    float acc[4][4][4];
    #pragma unroll
    for (int mt = 0; mt < 4; mt++)
        #pragma unroll
        for (int nt = 0; nt < 4; nt++)
            #pragma unroll
            for (int r = 0; r < 4; r++) acc[mt][nt][r] = 0.f;

    float4 ra0 = *(const float4*)(aPtr);
    float4 ra1 = *(const float4*)(aPtr + 4);
    if (FUSE_ADD) {
        float4 s0 = *(const float4*)(a2Ptr);
        float4 s1 = *(const float4*)(a2Ptr + 4);
        ra0.x += s0.x; ra0.y += s0.y; ra0.z += s0.z; ra0.w += s0.w;
        ra1.x += s1.x; ra1.y += s1.y; ra1.z += s1.z; ra1.w += s1.w;
    }
    float4 rb0 = *(const float4*)(bPtr);
    float4 rb1 = *(const float4*)(bPtr + 4);

    {
        uint32_t* as0 = As;
        uint32_t* bs0 = Bs;
        as0[(ks + 0) * TG_STRIDE + aRow] = f2tf32(ra0.x);
        as0[(ks + 1) * TG_STRIDE + aRow] = f2tf32(ra0.y);
        as0[(ks + 2) * TG_STRIDE + aRow] = f2tf32(ra0.z);
        as0[(ks + 3) * TG_STRIDE + aRow] = f2tf32(ra0.w);
        as0[(ks + 4) * TG_STRIDE + aRow] = f2tf32(ra1.x);
        as0[(ks + 5) * TG_STRIDE + aRow] = f2tf32(ra1.y);
        as0[(ks + 6) * TG_STRIDE + aRow] = f2tf32(ra1.z);
        as0[(ks + 7) * TG_STRIDE + aRow] = f2tf32(ra1.w);
        bs0[bRow * TG_STRIDE + bCol + 0] = f2tf32(rb0.x);
        bs0[bRow * TG_STRIDE + bCol + 1] = f2tf32(rb0.y);
        bs0[bRow * TG_STRIDE + bCol + 2] = f2tf32(rb0.z);
        bs0[bRow * TG_STRIDE + bCol + 3] = f2tf32(rb0.w);
        bs0[bRow * TG_STRIDE + bCol + 4] = f2tf32(rb1.x);
        bs0[bRow * TG_STRIDE + bCol + 5] = f2tf32(rb1.y);
        bs0[bRow * TG_STRIDE + bCol + 6] = f2tf32(rb1.z);
        bs0[bRow * TG_STRIDE + bCol + 7] = f2tf32(rb1.w);
    }
    __syncthreads();

    const int nTiles = K / BK;
    for (int kt = 0; kt < nTiles; kt++) {
        const uint32_t* asr = As + (kt & 1) * TG_BUF;
        const uint32_t* bsr = Bs + (kt & 1) * TG_BUF;

        const bool more = (kt + 1 < nTiles);
        if (more) {
            const float* ap = aPtr + (kt + 1) * BK;
            const float* bp = bPtr + (size_t)(kt + 1) * BK * bStep;
            ra0 = *(const float4*)(ap);
            ra1 = *(const float4*)(ap + 4);
            if (FUSE_ADD) {
                const float* ap2 = a2Ptr + (kt + 1) * BK;
                float4 s0 = *(const float4*)(ap2);
                float4 s1 = *(const float4*)(ap2 + 4);
                ra0.x += s0.x; ra0.y += s0.y; ra0.z += s0.z; ra0.w += s0.w;
                ra1.x += s1.x; ra1.y += s1.y; ra1.z += s1.z; ra1.w += s1.w;
            }
            rb0 = *(const float4*)(bp);
            rb1 = *(const float4*)(bp + 4);
        }

        #pragma unroll
        for (int kk = 0; kk < BK; kk += 8) {
            uint32_t afr[4][4];
            #pragma unroll
            for (int mt = 0; mt < 4; mt++) {
                const int m = warp_m + mt * 16 + g;
                afr[mt][0] = asr[(kk + c) * TG_STRIDE + m];
                afr[mt][1] = asr[(kk + c) * TG_STRIDE + m + 8];
                afr[mt][2] = asr[(kk + c + 4) * TG_STRIDE + m];
                afr[mt][3] = asr[(kk + c + 4) * TG_STRIDE + m + 8];
            }
            uint32_t bfr[4][2];
            #pragma unroll
            for (int nt = 0; nt < 4; nt++) {
                const int n = warp_n + nt * 8 + g;
                bfr[nt][0] = bsr[(kk + c) * TG_STRIDE + n];
                bfr[nt][1] = bsr[(kk + c + 4) * TG_STRIDE + n];
            }
            #pragma unroll
            for (int mt = 0; mt < 4; mt++)
                #pragma unroll
                for (int nt = 0; nt < 4; nt++)
                    mma_tf32(acc[mt][nt], afr[mt], bfr[nt]);
        }

        if (more) {
            uint32_t* asw = As + ((kt + 1) & 1) * TG_BUF;
            uint32_t* bsw = Bs + ((kt + 1) & 1) * TG_BUF;
            asw[(ks + 0) * TG_STRIDE + aRow] = f2tf32(ra0.x);
            asw[(ks + 1) * TG_STRIDE + aRow] = f2tf32(ra0.y);
            asw[(ks + 2) * TG_STRIDE + aRow] = f2tf32(ra0.z);
            asw[(ks + 3) * TG_STRIDE + aRow] = f2tf32(ra0.w);
            asw[(ks + 4) * TG_STRIDE + aRow] = f2tf32(ra1.x);
            asw[(ks + 5) * TG_STRIDE + aRow] = f2tf32(ra1.y);
            asw[(ks + 6) * TG_STRIDE + aRow] = f2tf32(ra1.z);
            asw[(ks + 7) * TG_STRIDE + aRow] = f2tf32(ra1.w);
            bsw[bRow * TG_STRIDE + bCol + 0] = f2tf32(rb0.x);
            bsw[bRow * TG_STRIDE + bCol + 1] = f2tf32(rb0.y);
            bsw[bRow * TG_STRIDE + bCol + 2] = f2tf32(rb0.z);
            bsw[bRow * TG_STRIDE + bCol + 3] = f2tf32(rb0.w);
            bsw[bRow * TG_STRIDE + bCol + 4] = f2tf32(rb1.x);
            bsw[bRow * TG_STRIDE + bCol + 5] = f2tf32(rb1.y);
            bsw[bRow * TG_STRIDE + bCol + 6] = f2tf32(rb1.z);
            bsw[bRow * TG_STRIDE + bCol + 7] = f2tf32(rb1.w);
            __syncthreads();
        }
    }

    #pragma unroll
    for (int mt = 0; mt < 4; mt++) {
        const int r0 = m0 + warp_m + mt * 16 + g;
        const int r1 = r0 + 8;
        float mf0 = 1.f, mf1 = 1.f;
        if (EPI == 2) {
            mf0 = mask[r0] ? 0.f : 1.f;
            mf1 = mask[r1] ? 0.f : 1.f;
        }
        #pragma unroll
        for (int nt = 0; nt < 4; nt++) {
            const int col = n0 + warp_n + nt * 8 + c * 2;
            const float2 bv = *(const float2*)&bias[col];
            float2 v0, v1;
            v0.x = acc[mt][nt][0] + bv.x;
            v0.y = acc[mt][nt][1] + bv.y;
            v1.x = acc[mt][nt][2] + bv.x;
            v1.y = acc[mt][nt][3] + bv.y;
            if (EPI == 1) {
                v0.x = fmaxf(v0.x, 0.f); v0.y = fmaxf(v0.y, 0.f);
                v1.x = fmaxf(v1.x, 0.f); v1.y = fmaxf(v1.y, 0.f);
            }
            if (EPI == 2) {
                v0.x *= mf0; v0.y *= mf0;
                v1.x *= mf1; v1.y *= mf1;
            }
            *(float2*)&C[(size_t)r0 * Nn + col] = v0;
            *(float2*)&C[(size_t)r1 * Nn + col] = v1;
        }
    }
}

// ---------------------------------------------------------------------------
// Deformable sampling v2 — issue-slot-minimized.
// One warp per (row, head). Phase 1 (lanes 0-15): warp softmax + per-sample
// corner byte-offsets/weights -> 64 (off,w) pairs in smem. Phase 2: lane
// mapping corner=lane>>3, chan_group=lane&7; 16 iters of
// {LDS.64 broadcast pair + LDG.128 gather + float4 FMA}. Epilogue: shfl-xor
// reduce over the 4 corner groups, lanes 0-7 STG.128 the 128B output row.
// ---------------------------------------------------------------------------
__global__ __launch_bounds__(256)
void sample_kernel(const float* __restrict__ value,
                   const float* __restrict__ off,
                   const float* __restrict__ aw,
                   const float* __restrict__ refp,
                   float* __restrict__ outp)
{
    __shared__ int2 pairs[8][64];          // [warp][sample*4+corner] = {byteoff, w}

    const int wid   = threadIdx.x >> 5;
    const int lane  = threadIdx.x & 31;
    const int gwarp = blockIdx.x * 8 + wid;
    const int h     = gwarp & 7;
    const int row   = gwarp >> 3;          // n*LQ + lq
    const int n     = row >> 13;           // LQ = 8192

    // ---- phase 1: softmax + corner precompute (lanes 0..15 hold data) ----
    float av = -1e30f;
    if (lane < 16) av = aw[(size_t)row * 128 + h * 16 + lane];
    float mx = av;
    #pragma unroll
    for (int o = 16; o > 0; o >>= 1) mx = fmaxf(mx, __shfl_xor_sync(0xffffffffu, mx, o));
    float e = (lane < 16) ? __expf(av - mx) : 0.f;
    float sm = e;
    #pragma unroll
    for (int o = 16; o > 0; o >>= 1) sm += __shfl_xor_sync(0xffffffffu, sm, o);
    const float w_aw = e / sm;

    if (lane < 16) {
        const int l = lane >> 2;
        const float2 of = *(const float2*)&off[(size_t)row * 256 + (h * 16 + lane) * 2];
        const float2 rp = *(const float2*)&refp[((size_t)row * 4 + l) * 2];
        const float Wl = c_lvl_wh[l];
        const int   Wi = (int)Wl;
        const int   start = c_lvl_start[l];

        const float x  = (rp.x + of.x / Wl) * Wl - 0.5f;
        const float y  = (rp.y + of.y / Wl) * Wl - 0.5f;
        const float x0 = floorf(x), y0 = floorf(y);
        const float dx = x - x0,   dy = y - y0;

        #pragma unroll
        for (int cc = 0; cc < 4; cc++) {
            const float cx = x0 + (float)(cc & 1);
            const float cy = y0 + (float)(cc >> 1);
            const float wgt = ((cc & 1) ? dx : 1.f - dx) * ((cc >> 1) ? dy : 1.f - dy);
            const bool valid = (cx >= 0.f) && (cx <= Wl - 1.f) &&
                               (cy >= 0.f) && (cy <= Wl - 1.f);
            const int ix = (int)fminf(fmaxf(cx, 0.f), Wl - 1.f);
            const int iy = (int)fminf(fmaxf(cy, 0.f), Wl - 1.f);
            const int idx = start + iy * Wi + ix;
            int2 pr;
            pr.x = idx << 10;              // byte offset: idx * 256 floats * 4B
            pr.y = __float_as_int(valid ? wgt * w_aw : 0.f);
            pairs[wid][lane * 4 + cc] = pr;
        }
    }
    __syncwarp();

    // ---- phase 2: float4 gather, corner-parallel lanes ----
    const int c  = lane >> 3;              // corner 0..3
    const int cg = lane & 7;               // 4-channel group 0..7
    const char* vbase = (const char*)value
                      + (size_t)n * (LIN * 1024) + h * 128 + cg * 16;

    float4 acc = make_float4(0.f, 0.f, 0.f, 0.f);
    #pragma unroll
    for (int s = 0; s < 16; s++) {
        const int2  pr = pairs[wid][s * 4 + c];
        const float wc = __int_as_float(pr.y);
        const float4 v = *(const float4*)(vbase + pr.x);
        acc.x += wc * v.x; acc.y += wc * v.y;
        acc.z += wc * v.z; acc.w += wc * v.w;
    }

    // ---- reduce over 4 corner groups (xor 8, xor 16) ----
    #pragma unroll
    for (int o = 8; o <= 16; o <<= 1) {
        acc.x += __shfl_xor_sync(0xffffffffu, acc.x, o);
        acc.y += __shfl_xor_sync(0xffffffffu, acc.y, o);
        acc.z += __shfl_xor_sync(0xffffffffu, acc.z, o);
        acc.w += __shfl_xor_sync(0xffffffffu, acc.w, o);
    }
    if (lane < 8)
        *(float4*)&outp[(size_t)row * 256 + h * 32 + lane * 4] = acc;
}

// ---------------------------------------------------------------------------
// Fused residual add + LayerNorm: out = LN(a + b). One warp per row (D=256).
// ---------------------------------------------------------------------------
__global__ __launch_bounds__(256)
void add_ln_kernel(const float* __restrict__ a, const float* __restrict__ b,
                   const float* __restrict__ g, const float* __restrict__ bet,
                   float* __restrict__ outp)
{
    const int row  = (blockIdx.x * blockDim.x + threadIdx.x) >> 5;
    const int lane = threadIdx.x & 31;
    const size_t base = (size_t)row * 256 + lane * 8;

    float v[8];
    float4 a0 = *(const float4*)&a[base];
    float4 a1 = *(const float4*)&a[base + 4];
    float4 b0 = *(const float4*)&b[base];
    float4 b1 = *(const float4*)&b[base + 4];
    v[0] = a0.x + b0.x; v[1] = a0.y + b0.y; v[2] = a0.z + b0.z; v[3] = a0.w + b0.w;
    v[4] = a1.x + b1.x; v[5] = a1.y + b1.y; v[6] = a1.z + b1.z; v[7] = a1.w + b1.w;

    float sum = 0.f, sq = 0.f;
    #pragma unroll
    for (int i = 0; i < 8; i++) { sum += v[i]; sq += v[i] * v[i]; }
    #pragma unroll
    for (int o = 16; o > 0; o >>= 1) {
        sum += __shfl_xor_sync(0xffffffffu, sum, o);
        sq  += __shfl_xor_sync(0xffffffffu, sq,  o);
    }
    const float mean = sum * (1.f / 256.f);
    const float var  = sq * (1.f / 256.f) - mean * mean;
    const float inv  = rsqrtf(var + 1e-5f);

    float4 g0 = *(const float4*)&g[lane * 8];
    float4 g1 = *(const float4*)&g[lane * 8 + 4];
    float4 e0 = *(const float4*)&bet[lane * 8];
    float4 e1 = *(const float4*)&bet[lane * 8 + 4];
    float gv[8] = {g0.x,g0.y,g0.z,g0.w,g1.x,g1.y,g1.z,g1.w};
    float ev[8] = {e0.x,e0.y,e0.z,e0.w,e1.x,e1.y,e1.z,e1.w};

    float o8[8];
    #pragma unroll
    for (int i = 0; i < 8; i++) o8[i] = (v[i] - mean) * inv * gv[i] + ev[i];
    float4 r0 = {o8[0], o8[1], o8[2], o8[3]};
    float4 r1 = {o8[4], o8[5], o8[6], o8[7]};
    *(float4*)&outp[base]     = r0;
    *(float4*)&outp[base + 4] = r1;
}

// ---------------------------------------------------------------------------
// Launch
// ---------------------------------------------------------------------------
extern "C" void kernel_launch(void* const* d_in, const int* in_sizes, int n_in,
                              void* d_out, int out_size)
{
    const float* tgt   = (const float*)d_in[0];
    const float* qpos  = (const float*)d_in[1];
    const float* refp  = (const float*)d_in[2];
    const float* src   = (const float*)d_in[3];
    // d_in[4] src_spatial_shapes (int64), d_in[5] level_start_index (int64): hardcoded
    const unsigned char* pmask = (const unsigned char*)d_in[6];
    const float* W_off = (const float*)d_in[7];
    const float* b_off = (const float*)d_in[8];
    const float* W_att = (const float*)d_in[9];
    const float* b_att = (const float*)d_in[10];
    const float* W_val = (const float*)d_in[11];
    const float* b_val = (const float*)d_in[12];
    const float* W_out = (const float*)d_in[13];
    const float* b_out = (const float*)d_in[14];
    const float* ln1_g = (const float*)d_in[15];
    const float* ln1_b = (const float*)d_in[16];
    const float* W_fc1 = (const float*)d_in[17];
    const float* b_fc1 = (const float*)d_in[18];
    const float* W_fc2 = (const float*)d_in[19];
    const float* b_fc2 = (const float*)d_in[20];
    const float* ln2_g = (const float*)d_in[21];
    const float* ln2_b = (const float*)d_in[22];
    float* out = (float*)d_out;

    float* base = nullptr;
    cudaGetSymbolAddress((void**)&base, g_scratch);
    float* smp = base + OFF_A;     // region A: sampled
    float* val = base + OFF_VAL;   // region B: value|off|aw, later ffn hidden
    float* ofb = base + OFF_OFF;
    float* awb = base + OFF_AW;
    float* hb  = base + OFF_B;
    float* x1  = base + OFF_C;     // region C
    float* h2  = base + OFF_D;     // region D

    // 1. value = mask(src @ W_val + b_val)   M=87040, N=256, K=256
    tgemm_kernel<2, false><<<dim3(2, 680), 256>>>(VROW, DM, DM, src, nullptr, W_val, b_val, val, pmask);
    // 2. off = (tgt+qpos) @ W_off + b_off    M=32768, N=256, K=256 (fused add)
    tgemm_kernel<0, true><<<dim3(2, 256), 256>>>(NROW, DM, DM, tgt, qpos, W_off, b_off, ofb, nullptr);
    // 3. aw  = (tgt+qpos) @ W_attn + b_attn  M=32768, N=128, K=256 (fused add)
    tgemm_kernel<0, true><<<dim3(1, 256), 256>>>(NROW, 128, DM, tgt, qpos, W_att, b_att, awb, nullptr);
    // 4. deformable sampling + softmax
    sample_kernel<<<(NROW * NHD) / 8, 256>>>(val, ofb, awb, refp, smp);
    // 5. attn_out = sampled @ W_out + b_out  -> h2 (region D)
    tgemm_kernel<0, false><<<dim3(2, 256), 256>>>(NROW, DM, DM, smp, nullptr, W_out, b_out, h2, nullptr);
    // 6. x1 = LN1(tgt + attn_out)
    add_ln_kernel<<<NROW / 8, 256>>>(tgt, h2, ln1_g, ln1_b, x1);
    // 7. h = relu(x1 @ W_fc1 + b_fc1)        M=32768, N=1024, K=256 (B region dead -> h)
    tgemm_kernel<1, false><<<dim3(8, 256), 256>>>(NROW, DFF, DM, x1, nullptr, W_fc1, b_fc1, hb, nullptr);
    // 8. h2 = h @ W_fc2 + b_fc2              M=32768, N=256, K=1024
    tgemm_kernel<0, false><<<dim3(2, 256), 256>>>(NROW, DM, DFF, hb, nullptr, W_fc2, b_fc2, h2, nullptr);
    // 9. out = LN2(x1 + h2)
    add_ln_kernel<<<NROW / 8, 256>>>(x1, h2, ln2_g, ln2_b, out);
}